// round 2
// baseline (speedup 1.0000x reference)
#include <cuda_runtime.h>

#define N_NODES   20000
#define N_EDGES   320000
#define NODE_DIM  128
#define EDGE_DIM  128
#define HD        256      // NUM_HEADS * HIDDEN_DIM
#define NUM_HEADS 8
#define HEAD_DIM  16
#define NEG_SLOPE 0.2f

// ---------------- device scratch (no allocs allowed) ----------------
__device__ float g_node_tbl[N_NODES * 640];          // [n][0:256]=ni_h, [256:512]=nj_h, [512:640]=node part of msg
__device__ float g_ex[N_EDGES * NUM_HEADS];          // exp(logit) per edge,head
__device__ float g_msg[N_EDGES * 128];               // per-edge message (pre-attention)
__device__ float g_node_sum[N_NODES * NUM_HEADS];    // softmax denominators
__device__ float g_agg[N_NODES * 128];               // aggregated messages
// prepacked weights: B matrices stored [K][N] for coalesced GEMM loads
__device__ float g_WN[128 * 640];
__device__ float g_bN[640];
__device__ float g_WE[128 * 384];                    // cols 0:256 = We.T, 256:384 = Wm_edge.T
__device__ float g_bE[384];                          // be ++ bm
__device__ float g_WO[128 * 128];                    // Wo.T

// ---------------- init ----------------
__global__ void zero_kernel() {
    int i = blockIdx.x * blockDim.x + threadIdx.x;
    const int NS = N_NODES * NUM_HEADS;
    const int TOT = NS + N_NODES * 128;
    if (i < NS) g_node_sum[i] = 0.f;
    else if (i < TOT) g_agg[i - NS] = 0.f;
}

__global__ void prepack_kernel(const float* __restrict__ Wni, const float* __restrict__ bni,
                               const float* __restrict__ Wnj, const float* __restrict__ bnj,
                               const float* __restrict__ We,  const float* __restrict__ be,
                               const float* __restrict__ Wm,  const float* __restrict__ bm,
                               const float* __restrict__ Wo) {
    int i = blockIdx.x * blockDim.x + threadIdx.x;
    // segments: WN 81920 | bN 640 | WE 49152 | bE 384 | WO 16384
    if (i < 81920) {
        int k = i / 640, j = i % 640;
        float v;
        if (j < 256)      v = Wni[j * 128 + k];
        else if (j < 512) v = Wnj[(j - 256) * 128 + k];
        else              v = Wm[(j - 512) * 256 + k];          // node half of Wm
        g_WN[i] = v;
    } else if (i < 81920 + 640) {
        int j = i - 81920;
        g_bN[j] = (j < 256) ? bni[j] : (j < 512 ? bnj[j - 256] : 0.f);
    } else if (i < 81920 + 640 + 49152) {
        int t = i - 81920 - 640;
        int k = t / 384, j = t % 384;
        float v;
        if (j < 256) v = We[j * 128 + k];
        else         v = Wm[(j - 256) * 256 + 128 + k];          // edge half of Wm
        g_WE[t] = v;
    } else if (i < 81920 + 640 + 49152 + 384) {
        int j = i - 81920 - 640 - 49152;
        g_bE[j] = (j < 256) ? be[j] : bm[j - 256];
    } else if (i < 81920 + 640 + 49152 + 384 + 16384) {
        int t = i - 81920 - 640 - 49152 - 384;
        int k = t / 128, n = t % 128;
        g_WO[t] = Wo[n * 128 + k];
    }
}

// ---------------- generic tiled GEMM: C[M,N] = A[M,K] @ B[K,N] + bias ----------------
// BM=64, BN=64, BK=16, 256 threads, 4x4 per thread
__global__ void gemm_kernel(const float* __restrict__ A, const float* __restrict__ B,
                            const float* __restrict__ bias, float* __restrict__ C,
                            int M, int N, int K) {
    __shared__ float As[16][64];
    __shared__ float Bs[16][64];
    int tid = threadIdx.x;
    int rt = tid >> 4, ct = tid & 15;
    int m0 = blockIdx.x * 64, n0 = blockIdx.y * 64;
    float acc[4][4] = {};
    int arow = tid >> 2, aq = tid & 3;
    int bk = tid >> 4, bq = tid & 15;
    for (int k0 = 0; k0 < K; k0 += 16) {
        float4 av = make_float4(0.f, 0.f, 0.f, 0.f);
        if (m0 + arow < M)
            av = *(const float4*)(A + (m0 + arow) * K + k0 + aq * 4);
        As[aq * 4 + 0][arow] = av.x; As[aq * 4 + 1][arow] = av.y;
        As[aq * 4 + 2][arow] = av.z; As[aq * 4 + 3][arow] = av.w;
        float4 bv = *(const float4*)(B + (k0 + bk) * N + n0 + bq * 4);
        *(float4*)&Bs[bk][bq * 4] = bv;
        __syncthreads();
#pragma unroll
        for (int kk = 0; kk < 16; kk++) {
            float a[4], b[4];
            *(float4*)a = *(float4*)&As[kk][rt * 4];
            *(float4*)b = *(float4*)&Bs[kk][ct * 4];
#pragma unroll
            for (int i = 0; i < 4; i++)
#pragma unroll
                for (int j = 0; j < 4; j++)
                    acc[i][j] += a[i] * b[j];
        }
        __syncthreads();
    }
#pragma unroll
    for (int i = 0; i < 4; i++) {
        int m = m0 + rt * 4 + i;
        if (m < M) {
            int n = n0 + ct * 4;
            float4 o;
            o.x = acc[i][0] + bias[n + 0];
            o.y = acc[i][1] + bias[n + 1];
            o.z = acc[i][2] + bias[n + 2];
            o.w = acc[i][3] + bias[n + 3];
            *(float4*)(C + m * N + n) = o;
        }
    }
}

// ---------------- edge GEMM + fused attention epilogue ----------------
// C[E,384] = edge_feat @ WE, grid.y in {0,1,2} selecting 128-col block.
// blocks 0,1 -> hidden (cols 0..255): gather + leaky + attn logit -> exp + atomic softmax denom
// block  2   -> messages (cols 256..383): + node part -> store g_msg
__global__ void edge_kernel(const float* __restrict__ EF, const int* __restrict__ EI,
                            const float* __restrict__ AP) {
    __shared__ float As[16][64];
    __shared__ float Bs[16][128];
    int tid = threadIdx.x;
    int rt = tid >> 4, ct = tid & 15;
    int e0 = blockIdx.x * 64;
    int cb = blockIdx.y;
    int n0 = cb * 128;
    float acc[4][8] = {};
    int arow = tid >> 2, aq = tid & 3;
    int bk = tid >> 4, bq = tid & 15;
    for (int k0 = 0; k0 < 128; k0 += 16) {
        float4 av = *(const float4*)(EF + (e0 + arow) * 128 + k0 + aq * 4);
        As[aq * 4 + 0][arow] = av.x; As[aq * 4 + 1][arow] = av.y;
        As[aq * 4 + 2][arow] = av.z; As[aq * 4 + 3][arow] = av.w;
        float4 b0 = *(const float4*)(g_WE + (k0 + bk) * 384 + n0 + bq * 4);
        float4 b1 = *(const float4*)(g_WE + (k0 + bk) * 384 + n0 + 64 + bq * 4);
        *(float4*)&Bs[bk][bq * 4] = b0;
        *(float4*)&Bs[bk][64 + bq * 4] = b1;
        __syncthreads();
#pragma unroll
        for (int kk = 0; kk < 16; kk++) {
            float a[4], b[8];
            *(float4*)a = *(float4*)&As[kk][rt * 4];
            *(float4*)b       = *(float4*)&Bs[kk][ct * 8];
            *(float4*)(b + 4) = *(float4*)&Bs[kk][ct * 8 + 4];
#pragma unroll
            for (int i = 0; i < 4; i++)
#pragma unroll
                for (int j = 0; j < 8; j++)
                    acc[i][j] += a[i] * b[j];
        }
        __syncthreads();
    }

    int col = ct * 8;  // 0..120, local within this 128-col block
    if (cb < 2) {
        int g0 = n0 + col;          // global hidden col 0..255
        int head = g0 >> 5;         // 0..7 (8 cols always within one head)
        int d0 = g0 & 31;
        float ap[8], bb[8];
        *(float4*)ap       = *(const float4*)(AP + head * 32 + d0);
        *(float4*)(ap + 4) = *(const float4*)(AP + head * 32 + d0 + 4);
        *(float4*)bb       = *(const float4*)(g_bE + g0);
        *(float4*)(bb + 4) = *(const float4*)(g_bE + g0 + 4);
#pragma unroll
        for (int i = 0; i < 4; i++) {
            int e = e0 + rt * 4 + i;
            int s = EI[e];
            int d = EI[N_EDGES + e];
            const float* ni = g_node_tbl + s * 640 + g0;
            const float* nj = g_node_tbl + d * 640 + 256 + g0;
            float niv[8], njv[8];
            *(float4*)niv       = *(const float4*)ni;
            *(float4*)(niv + 4) = *(const float4*)(ni + 4);
            *(float4*)njv       = *(const float4*)nj;
            *(float4*)(njv + 4) = *(const float4*)(nj + 4);
            float p = 0.f;
#pragma unroll
            for (int j = 0; j < 8; j++) {
                float h = acc[i][j] + bb[j] + niv[j] + njv[j];
                h = (h >= 0.f) ? h : NEG_SLOPE * h;
                p += h * ap[j];
            }
            // reduce the 4 lanes covering one head (32 hidden dims)
            p += __shfl_xor_sync(0xffffffffu, p, 1);
            p += __shfl_xor_sync(0xffffffffu, p, 2);
            if ((ct & 3) == 0) {
                float ex = expf(p);
                g_ex[e * 8 + head] = ex;
                atomicAdd(&g_node_sum[s * 8 + head], ex);
            }
        }
    } else {
#pragma unroll
        for (int i = 0; i < 4; i++) {
            int e = e0 + rt * 4 + i;
            int d = EI[N_EDGES + e];
            const float* nm = g_node_tbl + d * 640 + 512 + col;
            float nmv[8], bb[8];
            *(float4*)nmv       = *(const float4*)nm;
            *(float4*)(nmv + 4) = *(const float4*)(nm + 4);
            *(float4*)bb        = *(const float4*)(g_bE + 256 + col);
            *(float4*)(bb + 4)  = *(const float4*)(g_bE + 256 + col + 4);
            float4 o0, o1;
            o0.x = acc[i][0] + bb[0] + nmv[0];
            o0.y = acc[i][1] + bb[1] + nmv[1];
            o0.z = acc[i][2] + bb[2] + nmv[2];
            o0.w = acc[i][3] + bb[3] + nmv[3];
            o1.x = acc[i][4] + bb[4] + nmv[4];
            o1.y = acc[i][5] + bb[5] + nmv[5];
            o1.z = acc[i][6] + bb[6] + nmv[6];
            o1.w = acc[i][7] + bb[7] + nmv[7];
            *(float4*)(g_msg + e * 128 + col)     = o0;
            *(float4*)(g_msg + e * 128 + col + 4) = o1;
        }
    }
}

// ---------------- softmax-weight + scatter-aggregate: one warp per edge ----------------
__global__ void agg_kernel(const int* __restrict__ EI) {
    int e = (blockIdx.x * blockDim.x + threadIdx.x) >> 5;
    int lane = threadIdx.x & 31;
    if (e >= N_EDGES) return;
    int s = EI[e];
    int head = lane >> 2;  // lane*4 .. lane*4+3 all in head = lane/4 (HEAD_DIM=16)
    float ex = g_ex[e * 8 + head];
    float sum = g_node_sum[s * 8 + head];
    float w = ex / sum;
    float4 m = *(const float4*)(g_msg + e * 128 + lane * 4);
    float* dst = g_agg + s * 128 + lane * 4;
    asm volatile("red.global.add.v4.f32 [%0], {%1,%2,%3,%4};"
                 :: "l"(dst), "f"(m.x * w), "f"(m.y * w), "f"(m.z * w), "f"(m.w * w)
                 : "memory");
}

// ---------------- launch ----------------
extern "C" void kernel_launch(void* const* d_in, const int* in_sizes, int n_in,
                              void* d_out, int out_size) {
    const float* node_features = (const float*)d_in[0];
    const float* edge_features = (const float*)d_in[1];
    const int*   edge_index    = (const int*)d_in[2];
    const float* Wni = (const float*)d_in[3];
    const float* bni = (const float*)d_in[4];
    const float* Wnj = (const float*)d_in[5];
    const float* bnj = (const float*)d_in[6];
    const float* We  = (const float*)d_in[7];
    const float* be  = (const float*)d_in[8];
    const float* attn_proj = (const float*)d_in[9];
    const float* Wm  = (const float*)d_in[10];
    const float* bm  = (const float*)d_in[11];
    const float* Wo  = (const float*)d_in[12];
    const float* bo  = (const float*)d_in[13];
    float* out = (float*)d_out;

    float *pWN, *pbN, *pTbl, *pAgg, *pWO;
    cudaGetSymbolAddress((void**)&pWN,  g_WN);
    cudaGetSymbolAddress((void**)&pbN,  g_bN);
    cudaGetSymbolAddress((void**)&pTbl, g_node_tbl);
    cudaGetSymbolAddress((void**)&pAgg, g_agg);
    cudaGetSymbolAddress((void**)&pWO,  g_WO);

    const int ZTOT = N_NODES * NUM_HEADS + N_NODES * 128;
    zero_kernel<<<(ZTOT + 255) / 256, 256>>>();
    prepack_kernel<<<(81920 + 640 + 49152 + 384 + 16384 + 255) / 256, 256>>>(
        Wni, bni, Wnj, bnj, We, be, Wm, bm, Wo);

    // node tables: [20000,640] = node_features @ WN + bN
    gemm_kernel<<<dim3((N_NODES + 63) / 64, 640 / 64), 256>>>(
        node_features, pWN, pbN, pTbl, N_NODES, 640, 128);

    // edge pass: 5000 row blocks x 3 col blocks
    edge_kernel<<<dim3(N_EDGES / 64, 3), 256>>>(edge_features, edge_index, attn_proj);

    // aggregate: one warp per edge
    agg_kernel<<<N_EDGES / 8, 256>>>(edge_index);

    // output: [20000,128] = agg @ WO + bo
    gemm_kernel<<<dim3((N_NODES + 63) / 64, 128 / 64), 256>>>(
        pAgg, pWO, bo, out, N_NODES, 128, 128);
}